// round 1
// baseline (speedup 1.0000x reference)
#include <cuda_runtime.h>
#include <math.h>

#define HEADS  16
#define DHEAD  128
#define BATCH  2
#define SEQ    2048
#define DIM    2048
#define INNER  (HEADS * DHEAD)   // 2048
#define BH     (BATCH * HEADS)   // 32

// ---------------- scratch (allocation-free: __device__ globals) ----------------
__device__ float g_qlin [(size_t)BATCH * SEQ * INNER];        //  32 MB
__device__ float g_kvlin[(size_t)BATCH * SEQ * 2 * INNER];    //  64 MB
__device__ float g_Q    [(size_t)BH * SEQ * DHEAD];           //  32 MB
__device__ float g_Kt   [(size_t)BH * DHEAD * SEQ];           //  32 MB (transposed K)
__device__ float g_V    [(size_t)BH * SEQ * DHEAD];           //  32 MB
__device__ float g_S    [(size_t)BH * SEQ * SEQ];             // 512 MB
__device__ float g_attn [(size_t)BATCH * SEQ * INNER];        //  32 MB

// ---------------- generic batched SGEMM: C = A @ B (+bias) ----------------
// A: (M x K) row-major, contiguous (lda == K) -- true for all call sites.
// B: (K x N) row-major, contiguous (ldb == N) -- true for all call sites.
// C: row stride ldc; batch z offset = (z/cdiv)*sC + (z%cdiv)*sC2.
template<bool WITH_BIAS>
__global__ __launch_bounds__(256) void sgemm_kernel(
    const float* __restrict__ A, const float* __restrict__ Bm, float* __restrict__ C,
    int M, int Nn, int K,
    long long sA, long long sB, long long sC, long long sC2, int cdiv, int ldc,
    const float* __restrict__ bias)
{
    constexpr int BM = 128, BN = 128, BK = 16, TM = 8, TN = 8;
    __shared__ float As[BK][BM];
    __shared__ float Bs[BK][BN];

    int z = blockIdx.z;
    A  += (long long)z * sA;
    Bm += (long long)z * sB;
    C  += (long long)(z / cdiv) * sC + (long long)(z % cdiv) * sC2;

    int bx = blockIdx.x, by = blockIdx.y;
    int tid  = threadIdx.x;
    int trow = tid / 16;          // 0..15
    int tcol = tid % 16;          // 0..15

    const float* Ablk = A  + (long long)by * BM * K;
    const float* Bblk = Bm + bx * BN;

    int aRow = tid >> 2;          // 0..63
    int aCol = (tid & 3) * 4;     // 0,4,8,12
    int bRow = tid >> 5;          // 0..7
    int bCol = (tid & 31) * 4;    // 0..124

    float acc[TM][TN];
    #pragma unroll
    for (int m = 0; m < TM; m++)
        #pragma unroll
        for (int n = 0; n < TN; n++) acc[m][n] = 0.0f;

    for (int kt = 0; kt < K; kt += BK) {
        #pragma unroll
        for (int i = 0; i < 2; i++) {
            float4 a = *(const float4*)(Ablk + (long long)(aRow + i * 64) * K + kt + aCol);
            As[aCol + 0][aRow + i * 64] = a.x;
            As[aCol + 1][aRow + i * 64] = a.y;
            As[aCol + 2][aRow + i * 64] = a.z;
            As[aCol + 3][aRow + i * 64] = a.w;
        }
        #pragma unroll
        for (int i = 0; i < 2; i++) {
            *(float4*)&Bs[bRow + i * 8][bCol] =
                *(const float4*)(Bblk + (long long)(kt + bRow + i * 8) * Nn + bCol);
        }
        __syncthreads();

        #pragma unroll
        for (int kk = 0; kk < BK; kk++) {
            float ra[TM], rb[TN];
            *(float4*)&ra[0] = *(float4*)&As[kk][trow * TM];
            *(float4*)&ra[4] = *(float4*)&As[kk][trow * TM + 4];
            *(float4*)&rb[0] = *(float4*)&Bs[kk][tcol * TN];
            *(float4*)&rb[4] = *(float4*)&Bs[kk][tcol * TN + 4];
            #pragma unroll
            for (int m = 0; m < TM; m++)
                #pragma unroll
                for (int n = 0; n < TN; n++)
                    acc[m][n] += ra[m] * rb[n];
        }
        __syncthreads();
    }

    #pragma unroll
    for (int m = 0; m < TM; m++) {
        int row = by * BM + trow * TM + m;
        float* Crow = C + (long long)row * ldc + bx * BN + tcol * TN;
        #pragma unroll
        for (int n = 0; n < TN; n += 4) {
            float4 v = make_float4(acc[m][n], acc[m][n+1], acc[m][n+2], acc[m][n+3]);
            if (WITH_BIAS) {
                int col = bx * BN + tcol * TN + n;
                v.x += bias[col]; v.y += bias[col+1]; v.z += bias[col+2]; v.w += bias[col+3];
            }
            *(float4*)(Crow + n) = v;
        }
    }
}

// ---------------- rotary + scale + head split (+ K transpose) ----------------
// out[2i]   = t[2i]*cos[2i]   - t[2i+1]*sin[2i]
// out[2i+1] = t[2i+1]*cos[2i+1] + t[2i]*sin[2i+1]
__global__ __launch_bounds__(256) void rotary_kernel(
    const float* __restrict__ qlin, const float* __restrict__ kvlin,
    const float* __restrict__ rot,
    float* __restrict__ Q, float* __restrict__ Kt, float* __restrict__ V)
{
    int idx = blockIdx.x * blockDim.x + threadIdx.x;   // 0 .. B*N*H*64-1
    int p = idx & 63;                  // pair index
    int h = (idx >> 6) & (HEADS - 1);
    int n = (idx >> 10) & (SEQ - 1);
    int b = idx >> 21;
    int d0 = 2 * p;

    float c0, s0, c1, s1;
    sincosf(rot[n * DHEAD + d0],     &s0, &c0);
    sincosf(rot[n * DHEAD + d0 + 1], &s1, &c1);

    long long bh = (long long)b * HEADS + h;

    // Q: rotary + scale
    const float* ql = qlin + ((long long)(b * SEQ + n)) * INNER + h * DHEAD;
    float q0 = ql[d0], q1 = ql[d0 + 1];
    const float scale = 0.088388347648318447f;   // 128^-0.5
    float* Qp = Q + (bh * SEQ + n) * DHEAD;
    Qp[d0]     = (q0 * c0 - q1 * s0) * scale;
    Qp[d0 + 1] = (q1 * c1 + q0 * s1) * scale;

    // K: rotary, transposed write
    const float* kl = kvlin + ((long long)(b * SEQ + n)) * (2 * INNER) + h * DHEAD;
    float k0 = kl[d0], k1 = kl[d0 + 1];
    Kt[(bh * DHEAD + d0)     * SEQ + n] = k0 * c0 - k1 * s0;
    Kt[(bh * DHEAD + d0 + 1) * SEQ + n] = k1 * c1 + k0 * s1;

    // V: straight copy into (bh, n, d)
    const float* vl = kvlin + ((long long)(b * SEQ + n)) * (2 * INNER) + INNER + h * DHEAD;
    float* Vp = V + (bh * SEQ + n) * DHEAD;
    Vp[d0]     = vl[d0];
    Vp[d0 + 1] = vl[d0 + 1];
}

// ---------------- row softmax over S (rows of length 2048) ----------------
__global__ __launch_bounds__(256) void softmax_kernel(float* __restrict__ S)
{
    size_t row = blockIdx.x;
    float* p = S + row * (size_t)SEQ;
    int t = threadIdx.x;
    float4 v0 = ((float4*)p)[t * 2];
    float4 v1 = ((float4*)p)[t * 2 + 1];

    float mx = fmaxf(fmaxf(fmaxf(v0.x, v0.y), fmaxf(v0.z, v0.w)),
                     fmaxf(fmaxf(v1.x, v1.y), fmaxf(v1.z, v1.w)));
    #pragma unroll
    for (int o = 16; o; o >>= 1) mx = fmaxf(mx, __shfl_xor_sync(0xffffffffu, mx, o));

    __shared__ float redm[8];
    __shared__ float reds[8];
    int warp = t >> 5, lane = t & 31;
    if (lane == 0) redm[warp] = mx;
    __syncthreads();
    float m = redm[0];
    #pragma unroll
    for (int i = 1; i < 8; i++) m = fmaxf(m, redm[i]);

    v0.x = __expf(v0.x - m); v0.y = __expf(v0.y - m);
    v0.z = __expf(v0.z - m); v0.w = __expf(v0.w - m);
    v1.x = __expf(v1.x - m); v1.y = __expf(v1.y - m);
    v1.z = __expf(v1.z - m); v1.w = __expf(v1.w - m);

    float s = v0.x + v0.y + v0.z + v0.w + v1.x + v1.y + v1.z + v1.w;
    #pragma unroll
    for (int o = 16; o; o >>= 1) s += __shfl_xor_sync(0xffffffffu, s, o);
    if (lane == 0) reds[warp] = s;
    __syncthreads();
    float tot = 0.0f;
    #pragma unroll
    for (int i = 0; i < 8; i++) tot += reds[i];
    float inv = 1.0f / tot;

    v0.x *= inv; v0.y *= inv; v0.z *= inv; v0.w *= inv;
    v1.x *= inv; v1.y *= inv; v1.z *= inv; v1.w *= inv;
    ((float4*)p)[t * 2]     = v0;
    ((float4*)p)[t * 2 + 1] = v1;
}

// ---------------- launch ----------------
extern "C" void kernel_launch(void* const* d_in, const int* in_sizes, int n_in,
                              void* d_out, int out_size)
{
    const float* x   = (const float*)d_in[0];
    const float* rot = (const float*)d_in[1];
    const float* Wq  = (const float*)d_in[2];
    const float* Wkv = (const float*)d_in[3];
    const float* Wo  = (const float*)d_in[4];
    const float* bo  = (const float*)d_in[5];
    float* out = (float*)d_out;

    float *qlin, *kvlin, *Q, *Kt, *V, *S, *attn;
    cudaGetSymbolAddress((void**)&qlin,  g_qlin);
    cudaGetSymbolAddress((void**)&kvlin, g_kvlin);
    cudaGetSymbolAddress((void**)&Q,     g_Q);
    cudaGetSymbolAddress((void**)&Kt,    g_Kt);
    cudaGetSymbolAddress((void**)&V,     g_V);
    cudaGetSymbolAddress((void**)&S,     g_S);
    cudaGetSymbolAddress((void**)&attn,  g_attn);

    dim3 blk(256);
    const int M = BATCH * SEQ;   // 4096

    // 1) q_lin = x @ Wq           (4096 x 2048, K=2048)
    sgemm_kernel<false><<<dim3(DIM / 128, M / 128, 1), blk>>>(
        x, Wq, qlin, M, INNER, DIM, 0, 0, 0, 0, 1, INNER, nullptr);

    // 2) kv_lin = x @ Wkv         (4096 x 4096, K=2048)
    sgemm_kernel<false><<<dim3(2 * INNER / 128, M / 128, 1), blk>>>(
        x, Wkv, kvlin, M, 2 * INNER, DIM, 0, 0, 0, 0, 1, 2 * INNER, nullptr);

    // 3) rotary + split heads (+ scale on Q, transpose K)
    rotary_kernel<<<(BATCH * SEQ * HEADS * 64) / 256, blk>>>(qlin, kvlin, rot, Q, Kt, V);

    // 4) S = Q @ K^T   per (b,h): 2048 x 2048, K=128, batch 32
    sgemm_kernel<false><<<dim3(SEQ / 128, SEQ / 128, BH), blk>>>(
        Q, Kt, S, SEQ, SEQ, DHEAD,
        (long long)SEQ * DHEAD, (long long)DHEAD * SEQ,
        (long long)SEQ * SEQ, 0, 1, SEQ, nullptr);

    // 5) softmax over rows of S
    softmax_kernel<<<(unsigned)((size_t)BH * SEQ), blk>>>(S);

    // 6) attn_out = P @ V  per (b,h): 2048 x 128, K=2048; scatter to (b, n, h*d)
    sgemm_kernel<false><<<dim3(DHEAD / 128, SEQ / 128, BH), blk>>>(
        S, V, attn, SEQ, DHEAD, SEQ,
        (long long)SEQ * SEQ, (long long)SEQ * DHEAD,
        (long long)SEQ * INNER, (long long)DHEAD, HEADS, INNER, nullptr);

    // 7) out = attn_out @ Wo + bo  (4096 x 2048, K=2048)
    sgemm_kernel<true><<<dim3(DIM / 128, M / 128, 1), blk>>>(
        attn, Wo, out, M, DIM, INNER, 0, 0, 0, 0, 1, DIM, bo);
}

// round 2
// speedup vs baseline: 2.4281x; 2.4281x over previous
#include <cuda_runtime.h>
#include <math.h>
#include <stdint.h>

#define HEADS  16
#define DHEAD  128
#define BATCH  2
#define SEQ    2048
#define DIM    2048
#define INNER  (HEADS * DHEAD)   // 2048
#define BH     (BATCH * HEADS)   // 32

// ---------------- scratch (allocation-free: __device__ globals) ----------------
__device__ float g_qlin [(size_t)BATCH * SEQ * INNER];
__device__ float g_kvlin[(size_t)BATCH * SEQ * 2 * INNER];
__device__ float g_Q    [(size_t)BH * SEQ * DHEAD];
__device__ float g_Kt   [(size_t)BH * DHEAD * SEQ];
__device__ float g_V    [(size_t)BH * SEQ * DHEAD];
__device__ float g_S    [(size_t)BH * SEQ * SEQ];
__device__ float g_attn [(size_t)BATCH * SEQ * INNER];

// round fp32 -> tf32 (RN), result kept in fp32 container (low mantissa zeroed)
__device__ __forceinline__ float f2tf(float f) {
    uint32_t u;
    asm("cvt.rna.tf32.f32 %0, %1;" : "=r"(u) : "f"(f));
    return __uint_as_float(u);
}

// ---------------- TF32 tensor-core batched GEMM: C = A @ B (+bias) ----------------
// A: (M x K) row-major contiguous; B: (K x N) row-major contiguous (true at all sites).
// C batch offset = (z/cdiv)*sC + (z%cdiv)*sC2, row stride ldc.
template<bool WITH_BIAS>
__global__ __launch_bounds__(256) void tgemm_kernel(
    const float* __restrict__ A, const float* __restrict__ Bm, float* __restrict__ C,
    int M, int Nn, int K,
    long long sA, long long sB, long long sC, long long sC2, int cdiv, int ldc,
    const float* __restrict__ bias)
{
    constexpr int BK = 16;
    constexpr int PA = 24;    // As row pitch (floats)
    constexpr int PB = 132;   // Bs row pitch (floats) -> conflict-free b-frag reads

    __shared__ float As[128 * PA];   // [m][k], untransposed
    __shared__ float Bs[BK  * PB];   // [k][n]

    int z = blockIdx.z;
    A  += (long long)z * sA;
    Bm += (long long)z * sB;
    C  += (long long)(z / cdiv) * sC + (long long)(z % cdiv) * sC2;

    const int bx = blockIdx.x, by = blockIdx.y;
    const int tid  = threadIdx.x;
    const int lane = tid & 31;
    const int wid  = tid >> 5;
    const int warpm = wid >> 2;      // 0..1  -> 64 rows
    const int warpn = wid & 3;       // 0..3  -> 32 cols
    const int grp = lane >> 2;       // 0..7
    const int tig = lane & 3;        // 0..3

    // global->smem mapping
    const int aj   = tid & 3;            // k chunk (4 floats)
    const int arow = tid >> 2;           // 0..63 (and +64)
    const int bRow = tid >> 5;           // 0..7 (and +8)
    const int bCol = (tid & 31) * 4;

    const float* Ag = A  + ((long long)(by * 128 + arow)) * K + aj * 4;
    const float* Bg = Bm + bx * 128 + bCol;

    float c[4][4][4];
    #pragma unroll
    for (int i = 0; i < 4; i++)
        #pragma unroll
        for (int j = 0; j < 4; j++)
            #pragma unroll
            for (int r = 0; r < 4; r++) c[i][j][r] = 0.0f;

    for (int kt = 0; kt < K; kt += BK) {
        // load A tile [128][16] (coalesced, no transpose)
        #pragma unroll
        for (int i = 0; i < 2; i++) {
            float4 v = *(const float4*)(Ag + (long long)i * 64 * K + kt);
            float* d = &As[(arow + i * 64) * PA + aj * 4];
            d[0] = f2tf(v.x); d[1] = f2tf(v.y); d[2] = f2tf(v.z); d[3] = f2tf(v.w);
        }
        // load B tile [16][128]
        #pragma unroll
        for (int i = 0; i < 2; i++) {
            float4 v = *(const float4*)(Bg + (long long)(kt + bRow + i * 8) * Nn);
            float* d = &Bs[(bRow + i * 8) * PB + bCol];
            d[0] = f2tf(v.x); d[1] = f2tf(v.y); d[2] = f2tf(v.z); d[3] = f2tf(v.w);
        }
        __syncthreads();

        #pragma unroll
        for (int s = 0; s < 2; s++) {
            // physical k for this lane: logical k=tig -> 8s+2*tig ; k=tig+4 -> 8s+2*tig+1
            const int kk = 8 * s + 2 * tig;

            uint32_t a[4][4];
            #pragma unroll
            for (int im = 0; im < 4; im++) {
                int r0 = warpm * 64 + im * 16 + grp;
                float2 lo = *(const float2*)&As[r0 * PA + kk];         // a0, a2
                float2 hi = *(const float2*)&As[(r0 + 8) * PA + kk];   // a1, a3
                a[im][0] = __float_as_uint(lo.x);
                a[im][2] = __float_as_uint(lo.y);
                a[im][1] = __float_as_uint(hi.x);
                a[im][3] = __float_as_uint(hi.y);
            }
            uint32_t b[4][2];
            #pragma unroll
            for (int in_ = 0; in_ < 4; in_++) {
                int n0 = warpn * 32 + in_ * 8 + grp;
                b[in_][0] = __float_as_uint(Bs[kk * PB + n0]);
                b[in_][1] = __float_as_uint(Bs[(kk + 1) * PB + n0]);
            }
            #pragma unroll
            for (int im = 0; im < 4; im++)
                #pragma unroll
                for (int in_ = 0; in_ < 4; in_++) {
                    asm volatile(
                        "mma.sync.aligned.m16n8k8.row.col.f32.tf32.tf32.f32 "
                        "{%0,%1,%2,%3}, {%4,%5,%6,%7}, {%8,%9}, {%0,%1,%2,%3};"
                        : "+f"(c[im][in_][0]), "+f"(c[im][in_][1]),
                          "+f"(c[im][in_][2]), "+f"(c[im][in_][3])
                        : "r"(a[im][0]), "r"(a[im][1]), "r"(a[im][2]), "r"(a[im][3]),
                          "r"(b[in_][0]), "r"(b[in_][1]));
                }
        }
        __syncthreads();
    }

    // epilogue
    #pragma unroll
    for (int im = 0; im < 4; im++) {
        int row0 = by * 128 + warpm * 64 + im * 16 + grp;
        #pragma unroll
        for (int in_ = 0; in_ < 4; in_++) {
            int col0 = bx * 128 + warpn * 32 + in_ * 8 + 2 * tig;
            float2 v0 = make_float2(c[im][in_][0], c[im][in_][1]);
            float2 v1 = make_float2(c[im][in_][2], c[im][in_][3]);
            if (WITH_BIAS) {
                v0.x += bias[col0]; v0.y += bias[col0 + 1];
                v1.x += bias[col0]; v1.y += bias[col0 + 1];
            }
            *(float2*)(C + (long long)row0 * ldc + col0)       = v0;
            *(float2*)(C + (long long)(row0 + 8) * ldc + col0) = v1;
        }
    }
}

// ---------------- rotary + scale + head split (+ K transpose) ----------------
__global__ __launch_bounds__(256) void rotary_kernel(
    const float* __restrict__ qlin, const float* __restrict__ kvlin,
    const float* __restrict__ rot,
    float* __restrict__ Q, float* __restrict__ Kt, float* __restrict__ V)
{
    int idx = blockIdx.x * blockDim.x + threadIdx.x;
    int p = idx & 63;
    int h = (idx >> 6) & (HEADS - 1);
    int n = (idx >> 10) & (SEQ - 1);
    int b = idx >> 21;
    int d0 = 2 * p;

    float c0, s0, c1, s1;
    sincosf(rot[n * DHEAD + d0],     &s0, &c0);
    sincosf(rot[n * DHEAD + d0 + 1], &s1, &c1);

    long long bh = (long long)b * HEADS + h;

    const float* ql = qlin + ((long long)(b * SEQ + n)) * INNER + h * DHEAD;
    float q0 = ql[d0], q1 = ql[d0 + 1];
    const float scale = 0.088388347648318447f;
    float* Qp = Q + (bh * SEQ + n) * DHEAD;
    Qp[d0]     = (q0 * c0 - q1 * s0) * scale;
    Qp[d0 + 1] = (q1 * c1 + q0 * s1) * scale;

    const float* kl = kvlin + ((long long)(b * SEQ + n)) * (2 * INNER) + h * DHEAD;
    float k0 = kl[d0], k1 = kl[d0 + 1];
    Kt[(bh * DHEAD + d0)     * SEQ + n] = k0 * c0 - k1 * s0;
    Kt[(bh * DHEAD + d0 + 1) * SEQ + n] = k1 * c1 + k0 * s1;

    const float* vl = kvlin + ((long long)(b * SEQ + n)) * (2 * INNER) + INNER + h * DHEAD;
    float* Vp = V + (bh * SEQ + n) * DHEAD;
    Vp[d0]     = vl[d0];
    Vp[d0 + 1] = vl[d0 + 1];
}

// ---------------- row softmax over S (rows of length 2048) ----------------
__global__ __launch_bounds__(256) void softmax_kernel(float* __restrict__ S)
{
    size_t row = blockIdx.x;
    float* p = S + row * (size_t)SEQ;
    int t = threadIdx.x;
    float4 v0 = ((float4*)p)[t * 2];
    float4 v1 = ((float4*)p)[t * 2 + 1];

    float mx = fmaxf(fmaxf(fmaxf(v0.x, v0.y), fmaxf(v0.z, v0.w)),
                     fmaxf(fmaxf(v1.x, v1.y), fmaxf(v1.z, v1.w)));
    #pragma unroll
    for (int o = 16; o; o >>= 1) mx = fmaxf(mx, __shfl_xor_sync(0xffffffffu, mx, o));

    __shared__ float redm[8];
    __shared__ float reds[8];
    int warp = t >> 5, lane = t & 31;
    if (lane == 0) redm[warp] = mx;
    __syncthreads();
    float m = redm[0];
    #pragma unroll
    for (int i = 1; i < 8; i++) m = fmaxf(m, redm[i]);

    v0.x = __expf(v0.x - m); v0.y = __expf(v0.y - m);
    v0.z = __expf(v0.z - m); v0.w = __expf(v0.w - m);
    v1.x = __expf(v1.x - m); v1.y = __expf(v1.y - m);
    v1.z = __expf(v1.z - m); v1.w = __expf(v1.w - m);

    float s = v0.x + v0.y + v0.z + v0.w + v1.x + v1.y + v1.z + v1.w;
    #pragma unroll
    for (int o = 16; o; o >>= 1) s += __shfl_xor_sync(0xffffffffu, s, o);
    if (lane == 0) reds[warp] = s;
    __syncthreads();
    float tot = 0.0f;
    #pragma unroll
    for (int i = 0; i < 8; i++) tot += reds[i];
    float inv = 1.0f / tot;

    v0.x *= inv; v0.y *= inv; v0.z *= inv; v0.w *= inv;
    v1.x *= inv; v1.y *= inv; v1.z *= inv; v1.w *= inv;
    ((float4*)p)[t * 2]     = v0;
    ((float4*)p)[t * 2 + 1] = v1;
}

// ---------------- launch ----------------
extern "C" void kernel_launch(void* const* d_in, const int* in_sizes, int n_in,
                              void* d_out, int out_size)
{
    const float* x   = (const float*)d_in[0];
    const float* rot = (const float*)d_in[1];
    const float* Wq  = (const float*)d_in[2];
    const float* Wkv = (const float*)d_in[3];
    const float* Wo  = (const float*)d_in[4];
    const float* bo  = (const float*)d_in[5];
    float* out = (float*)d_out;

    float *qlin, *kvlin, *Q, *Kt, *V, *S, *attn;
    cudaGetSymbolAddress((void**)&qlin,  g_qlin);
    cudaGetSymbolAddress((void**)&kvlin, g_kvlin);
    cudaGetSymbolAddress((void**)&Q,     g_Q);
    cudaGetSymbolAddress((void**)&Kt,    g_Kt);
    cudaGetSymbolAddress((void**)&V,     g_V);
    cudaGetSymbolAddress((void**)&S,     g_S);
    cudaGetSymbolAddress((void**)&attn,  g_attn);

    dim3 blk(256);
    const int M = BATCH * SEQ;   // 4096

    // 1) q_lin = x @ Wq
    tgemm_kernel<false><<<dim3(DIM / 128, M / 128, 1), blk>>>(
        x, Wq, qlin, M, INNER, DIM, 0, 0, 0, 0, 1, INNER, nullptr);

    // 2) kv_lin = x @ Wkv
    tgemm_kernel<false><<<dim3(2 * INNER / 128, M / 128, 1), blk>>>(
        x, Wkv, kvlin, M, 2 * INNER, DIM, 0, 0, 0, 0, 1, 2 * INNER, nullptr);

    // 3) rotary + split heads (+ scale on Q, transpose K)
    rotary_kernel<<<(BATCH * SEQ * HEADS * 64) / 256, blk>>>(qlin, kvlin, rot, Q, Kt, V);

    // 4) S = Q @ K^T   per (b,h)
    tgemm_kernel<false><<<dim3(SEQ / 128, SEQ / 128, BH), blk>>>(
        Q, Kt, S, SEQ, SEQ, DHEAD,
        (long long)SEQ * DHEAD, (long long)DHEAD * SEQ,
        (long long)SEQ * SEQ, 0, 1, SEQ, nullptr);

    // 5) softmax
    softmax_kernel<<<(unsigned)((size_t)BH * SEQ), blk>>>(S);

    // 6) attn_out = P @ V  per (b,h), scatter to (b, n, h*d)
    tgemm_kernel<false><<<dim3(DHEAD / 128, SEQ / 128, BH), blk>>>(
        S, V, attn, SEQ, DHEAD, SEQ,
        (long long)SEQ * SEQ, (long long)SEQ * DHEAD,
        (long long)SEQ * INNER, (long long)DHEAD, HEADS, INNER, nullptr);

    // 7) out = attn_out @ Wo + bo
    tgemm_kernel<true><<<dim3(DIM / 128, M / 128, 1), blk>>>(
        attn, Wo, out, M, DIM, INNER, 0, 0, 0, 0, 1, DIM, bo);
}

// round 3
// speedup vs baseline: 2.5121x; 1.0346x over previous
#include <cuda_runtime.h>
#include <math.h>
#include <stdint.h>

#define HEADS  16
#define DHEAD  128
#define BATCH  2
#define SEQ    2048
#define DIM    2048
#define INNER  (HEADS * DHEAD)   // 2048
#define BH     (BATCH * HEADS)   // 32

// ---------------- scratch (allocation-free: __device__ globals) ----------------
__device__ float g_qlin [(size_t)BATCH * SEQ * INNER];
__device__ float g_kvlin[(size_t)BATCH * SEQ * 2 * INNER];
__device__ float g_Q    [(size_t)BH * SEQ * DHEAD];     // (bh, n, d), tf32-rounded, scaled
__device__ float g_K    [(size_t)BH * SEQ * DHEAD];     // (bh, n, d), tf32-rounded
__device__ float g_Vt   [(size_t)BH * DHEAD * SEQ];     // (bh, d, n), tf32-rounded
__device__ float g_attn [(size_t)BATCH * SEQ * INNER];

// round fp32 -> tf32 (RN), kept in fp32 container
__device__ __forceinline__ float f2tf(float f) {
    uint32_t u;
    asm("cvt.rna.tf32.f32 %0, %1;" : "=r"(u) : "f"(f));
    return __uint_as_float(u);
}
__device__ __forceinline__ uint32_t f2tfu(float f) {
    uint32_t u;
    asm("cvt.rna.tf32.f32 %0, %1;" : "=r"(u) : "f"(f));
    return u;
}

#define MMA_TF32(C, A0, A1, A2, A3, B0, B1)                                   \
    asm volatile(                                                             \
        "mma.sync.aligned.m16n8k8.row.col.f32.tf32.tf32.f32 "                 \
        "{%0,%1,%2,%3}, {%4,%5,%6,%7}, {%8,%9}, {%0,%1,%2,%3};"               \
        : "+f"((C)[0]), "+f"((C)[1]), "+f"((C)[2]), "+f"((C)[3])              \
        : "r"(A0), "r"(A1), "r"(A2), "r"(A3), "r"(B0), "r"(B1))

// ---------------- TF32 tensor-core batched GEMM: C = A @ B (+bias) ----------------
template<bool WITH_BIAS>
__global__ __launch_bounds__(256) void tgemm_kernel(
    const float* __restrict__ A, const float* __restrict__ Bm, float* __restrict__ C,
    int M, int Nn, int K,
    long long sA, long long sB, long long sC, long long sC2, int cdiv, int ldc,
    const float* __restrict__ bias)
{
    constexpr int BK = 16;
    constexpr int PA = 24;
    constexpr int PB = 132;

    __shared__ float As[128 * PA];
    __shared__ float Bs[BK  * PB];

    int z = blockIdx.z;
    A  += (long long)z * sA;
    Bm += (long long)z * sB;
    C  += (long long)(z / cdiv) * sC + (long long)(z % cdiv) * sC2;

    const int bx = blockIdx.x, by = blockIdx.y;
    const int tid  = threadIdx.x;
    const int lane = tid & 31;
    const int wid  = tid >> 5;
    const int warpm = wid >> 2;
    const int warpn = wid & 3;
    const int grp = lane >> 2;
    const int tig = lane & 3;

    const int aj   = tid & 3;
    const int arow = tid >> 2;
    const int bRow = tid >> 5;
    const int bCol = (tid & 31) * 4;

    const float* Ag = A  + ((long long)(by * 128 + arow)) * K + aj * 4;
    const float* Bg = Bm + bx * 128 + bCol;

    float c[4][4][4];
    #pragma unroll
    for (int i = 0; i < 4; i++)
        #pragma unroll
        for (int j = 0; j < 4; j++)
            #pragma unroll
            for (int r = 0; r < 4; r++) c[i][j][r] = 0.0f;

    for (int kt = 0; kt < K; kt += BK) {
        #pragma unroll
        for (int i = 0; i < 2; i++) {
            float4 v = *(const float4*)(Ag + (long long)i * 64 * K + kt);
            float* d = &As[(arow + i * 64) * PA + aj * 4];
            d[0] = f2tf(v.x); d[1] = f2tf(v.y); d[2] = f2tf(v.z); d[3] = f2tf(v.w);
        }
        #pragma unroll
        for (int i = 0; i < 2; i++) {
            float4 v = *(const float4*)(Bg + (long long)(kt + bRow + i * 8) * Nn);
            float* d = &Bs[(bRow + i * 8) * PB + bCol];
            d[0] = f2tf(v.x); d[1] = f2tf(v.y); d[2] = f2tf(v.z); d[3] = f2tf(v.w);
        }
        __syncthreads();

        #pragma unroll
        for (int s = 0; s < 2; s++) {
            const int kk = 8 * s + 2 * tig;
            uint32_t a[4][4];
            #pragma unroll
            for (int im = 0; im < 4; im++) {
                int r0 = warpm * 64 + im * 16 + grp;
                float2 lo = *(const float2*)&As[r0 * PA + kk];
                float2 hi = *(const float2*)&As[(r0 + 8) * PA + kk];
                a[im][0] = __float_as_uint(lo.x);
                a[im][2] = __float_as_uint(lo.y);
                a[im][1] = __float_as_uint(hi.x);
                a[im][3] = __float_as_uint(hi.y);
            }
            uint32_t b[4][2];
            #pragma unroll
            for (int in_ = 0; in_ < 4; in_++) {
                int n0 = warpn * 32 + in_ * 8 + grp;
                b[in_][0] = __float_as_uint(Bs[kk * PB + n0]);
                b[in_][1] = __float_as_uint(Bs[(kk + 1) * PB + n0]);
            }
            #pragma unroll
            for (int im = 0; im < 4; im++)
                #pragma unroll
                for (int in_ = 0; in_ < 4; in_++)
                    MMA_TF32(c[im][in_], a[im][0], a[im][1], a[im][2], a[im][3],
                             b[in_][0], b[in_][1]);
        }
        __syncthreads();
    }

    #pragma unroll
    for (int im = 0; im < 4; im++) {
        int row0 = by * 128 + warpm * 64 + im * 16 + grp;
        #pragma unroll
        for (int in_ = 0; in_ < 4; in_++) {
            int col0 = bx * 128 + warpn * 32 + in_ * 8 + 2 * tig;
            float2 v0 = make_float2(c[im][in_][0], c[im][in_][1]);
            float2 v1 = make_float2(c[im][in_][2], c[im][in_][3]);
            if (WITH_BIAS) {
                v0.x += bias[col0]; v0.y += bias[col0 + 1];
                v1.x += bias[col0]; v1.y += bias[col0 + 1];
            }
            *(float2*)(C + (long long)row0 * ldc + col0)       = v0;
            *(float2*)(C + (long long)(row0 + 8) * ldc + col0) = v1;
        }
    }
}

// ---------------- rotary + scale + head split; K natural, V transposed ----------------
__global__ __launch_bounds__(256) void rotary_kernel(
    const float* __restrict__ qlin, const float* __restrict__ kvlin,
    const float* __restrict__ rot,
    float* __restrict__ Q, float* __restrict__ K, float* __restrict__ Vt)
{
    int idx = blockIdx.x * blockDim.x + threadIdx.x;
    int p = idx & 63;
    int h = (idx >> 6) & (HEADS - 1);
    int n = (idx >> 10) & (SEQ - 1);
    int b = idx >> 21;
    int d0 = 2 * p;

    float c0, s0, c1, s1;
    sincosf(rot[n * DHEAD + d0],     &s0, &c0);
    sincosf(rot[n * DHEAD + d0 + 1], &s1, &c1);

    long long bh = (long long)b * HEADS + h;

    const float* ql = qlin + ((long long)(b * SEQ + n)) * INNER + h * DHEAD;
    float q0 = ql[d0], q1 = ql[d0 + 1];
    const float scale = 0.088388347648318447f;
    float* Qp = Q + (bh * SEQ + n) * DHEAD;
    Qp[d0]     = f2tf((q0 * c0 - q1 * s0) * scale);
    Qp[d0 + 1] = f2tf((q1 * c1 + q0 * s1) * scale);

    const float* kl = kvlin + ((long long)(b * SEQ + n)) * (2 * INNER) + h * DHEAD;
    float k0 = kl[d0], k1 = kl[d0 + 1];
    float* Kp = K + (bh * SEQ + n) * DHEAD;
    Kp[d0]     = f2tf(k0 * c0 - k1 * s0);
    Kp[d0 + 1] = f2tf(k1 * c1 + k0 * s1);

    const float* vl = kvlin + ((long long)(b * SEQ + n)) * (2 * INNER) + INNER + h * DHEAD;
    Vt[(bh * DHEAD + d0)     * SEQ + n] = f2tf(vl[d0]);
    Vt[(bh * DHEAD + d0 + 1) * SEQ + n] = f2tf(vl[d0 + 1]);
}

// ---------------- fused flash attention ----------------
// block = (qblk, bh); 256 threads, warp w owns Q rows 16w..16w+15 (full 128 cols of O).
// smem (floats): Qs[128][132] @0, Ks[2][64][132] @16896, Vs[2][128][68] @33792.
#define PQ 132
#define PK 132
#define PV 68
#define QS_OFF 0
#define KS_OFF 16896
#define KS_STR 8448
#define VS_OFF 33792
#define VS_STR 8704
#define FLASH_SMEM 204800
#define NTILE 32

__global__ __launch_bounds__(256) void flash_kernel(
    const float* __restrict__ Qg_, const float* __restrict__ Kg_,
    const float* __restrict__ Vg_, float* __restrict__ attn)
{
    extern __shared__ float sm[];
    float* Qs = sm + QS_OFF;
    float* Ks = sm + KS_OFF;
    float* Vs = sm + VS_OFF;

    const int qblk = blockIdx.x, bh = blockIdx.y;
    const int b = bh >> 4, h = bh & 15;
    const int tid = threadIdx.x, lane = tid & 31, wid = tid >> 5;
    const int grp = lane >> 2, tig = lane & 3;

    const float* Qg = Qg_ + ((long long)bh * SEQ + qblk * 128) * DHEAD;
    const float* Kg = Kg_ + (long long)bh * SEQ * DHEAD;
    const float* Vg = Vg_ + (long long)bh * DHEAD * SEQ;

    // stage Q (128 x 128)
    #pragma unroll
    for (int i = 0; i < 16; i++) {
        int ch = tid + 256 * i;
        int row = ch >> 5, c4 = (ch & 31) * 4;
        *(float4*)&Qs[row * PQ + c4] = *(const float4*)(Qg + row * DHEAD + c4);
    }

    // cp.async tile issue: one commit group per tile (K 64x128 + Vt 128x64)
    auto issue = [&](int it, int buf) {
        const float* ks = Kg + it * 64 * DHEAD;
        #pragma unroll
        for (int i = 0; i < 8; i++) {
            int ch = tid + 256 * i;
            int row = ch >> 5, c4 = (ch & 31) * 4;
            uint32_t d = (uint32_t)__cvta_generic_to_shared(&Ks[buf * KS_STR + row * PK + c4]);
            asm volatile("cp.async.cg.shared.global [%0], [%1], 16;"
                         :: "r"(d), "l"(ks + row * DHEAD + c4));
        }
        const float* vs = Vg + it * 64;
        #pragma unroll
        for (int i = 0; i < 8; i++) {
            int ch = tid + 256 * i;
            int row = ch >> 4, c4 = (ch & 15) * 4;
            uint32_t d = (uint32_t)__cvta_generic_to_shared(&Vs[buf * VS_STR + row * PV + c4]);
            asm volatile("cp.async.cg.shared.global [%0], [%1], 16;"
                         :: "r"(d), "l"(vs + row * SEQ + c4));
        }
        asm volatile("cp.async.commit_group;");
    };

    issue(0, 0);
    issue(1, 1);

    float o[16][4];
    #pragma unroll
    for (int f = 0; f < 16; f++)
        #pragma unroll
        for (int r = 0; r < 4; r++) o[f][r] = 0.0f;
    float m0 = -1e30f, m1 = -1e30f, l0 = 0.0f, l1 = 0.0f;

    const int rowA = 16 * wid + grp;

    for (int it = 0; it < NTILE; it++) {
        if (it < NTILE - 1) asm volatile("cp.async.wait_group 1;");
        else                asm volatile("cp.async.wait_group 0;");
        __syncthreads();

        const float* kb = Ks + (it & 1) * KS_STR;
        const float* vb = Vs + (it & 1) * VS_STR;

        // ---- S = Q @ K^T (16 rows x 64 cols per warp) ----
        float sc[8][4];
        #pragma unroll
        for (int f = 0; f < 8; f++)
            #pragma unroll
            for (int r = 0; r < 4; r++) sc[f][r] = 0.0f;

        #pragma unroll
        for (int s = 0; s < 16; s++) {
            const int kk = 8 * s + 2 * tig;
            float2 qa = *(const float2*)&Qs[rowA * PQ + kk];
            float2 qb = *(const float2*)&Qs[(rowA + 8) * PQ + kk];
            uint32_t a0 = __float_as_uint(qa.x), a1 = __float_as_uint(qb.x);
            uint32_t a2 = __float_as_uint(qa.y), a3 = __float_as_uint(qb.y);
            #pragma unroll
            for (int f = 0; f < 8; f++) {
                float2 bk = *(const float2*)&kb[(8 * f + grp) * PK + kk];
                MMA_TF32(sc[f], a0, a1, a2, a3,
                         __float_as_uint(bk.x), __float_as_uint(bk.y));
            }
        }

        // ---- online softmax ----
        float mx0 = -1e30f, mx1 = -1e30f;
        #pragma unroll
        for (int f = 0; f < 8; f++) {
            mx0 = fmaxf(mx0, fmaxf(sc[f][0], sc[f][1]));
            mx1 = fmaxf(mx1, fmaxf(sc[f][2], sc[f][3]));
        }
        mx0 = fmaxf(mx0, __shfl_xor_sync(0xffffffffu, mx0, 1));
        mx0 = fmaxf(mx0, __shfl_xor_sync(0xffffffffu, mx0, 2));
        mx1 = fmaxf(mx1, __shfl_xor_sync(0xffffffffu, mx1, 1));
        mx1 = fmaxf(mx1, __shfl_xor_sync(0xffffffffu, mx1, 2));

        float mn0 = fmaxf(m0, mx0), mn1 = fmaxf(m1, mx1);
        float r0 = __expf(m0 - mn0), r1 = __expf(m1 - mn1);
        l0 *= r0; l1 *= r1;
        #pragma unroll
        for (int f = 0; f < 16; f++) {
            o[f][0] *= r0; o[f][1] *= r0;
            o[f][2] *= r1; o[f][3] *= r1;
        }

        uint32_t pu[8][4];
        float rs0 = 0.0f, rs1 = 0.0f;
        #pragma unroll
        for (int f = 0; f < 8; f++) {
            float p0 = __expf(sc[f][0] - mn0);
            float p1 = __expf(sc[f][1] - mn0);
            float p2 = __expf(sc[f][2] - mn1);
            float p3 = __expf(sc[f][3] - mn1);
            rs0 += p0 + p1; rs1 += p2 + p3;
            pu[f][0] = f2tfu(p0); pu[f][1] = f2tfu(p1);
            pu[f][2] = f2tfu(p2); pu[f][3] = f2tfu(p3);
        }
        rs0 += __shfl_xor_sync(0xffffffffu, rs0, 1);
        rs0 += __shfl_xor_sync(0xffffffffu, rs0, 2);
        rs1 += __shfl_xor_sync(0xffffffffu, rs1, 1);
        rs1 += __shfl_xor_sync(0xffffffffu, rs1, 2);
        l0 += rs0; l1 += rs1;
        m0 = mn0; m1 = mn1;

        // ---- O += P @ V ----
        #pragma unroll
        for (int s = 0; s < 8; s++) {
            uint32_t a0 = pu[s][0], a1 = pu[s][2], a2 = pu[s][1], a3 = pu[s][3];
            const int kk = 8 * s + 2 * tig;
            #pragma unroll
            for (int f = 0; f < 16; f++) {
                float2 bv = *(const float2*)&vb[(8 * f + grp) * PV + kk];
                MMA_TF32(o[f], a0, a1, a2, a3,
                         __float_as_uint(bv.x), __float_as_uint(bv.y));
            }
        }

        __syncthreads();
        if (it + 2 < NTILE) issue(it + 2, it & 1);
    }

    // epilogue: O /= l, scatter to (b, n, h*d)
    float inv0 = 1.0f / l0, inv1 = 1.0f / l1;
    int nrow = qblk * 128 + 16 * wid + grp;
    float* outp = attn + ((long long)(b * SEQ + nrow)) * INNER + h * DHEAD;
    #pragma unroll
    for (int f = 0; f < 16; f++) {
        int col = 8 * f + 2 * tig;
        *(float2*)(outp + col) = make_float2(o[f][0] * inv0, o[f][1] * inv0);
        *(float2*)(outp + (long long)8 * INNER + col) = make_float2(o[f][2] * inv1, o[f][3] * inv1);
    }
}

// ---------------- launch ----------------
extern "C" void kernel_launch(void* const* d_in, const int* in_sizes, int n_in,
                              void* d_out, int out_size)
{
    const float* x   = (const float*)d_in[0];
    const float* rot = (const float*)d_in[1];
    const float* Wq  = (const float*)d_in[2];
    const float* Wkv = (const float*)d_in[3];
    const float* Wo  = (const float*)d_in[4];
    const float* bo  = (const float*)d_in[5];
    float* out = (float*)d_out;

    float *qlin, *kvlin, *Q, *K, *Vt, *attn;
    cudaGetSymbolAddress((void**)&qlin,  g_qlin);
    cudaGetSymbolAddress((void**)&kvlin, g_kvlin);
    cudaGetSymbolAddress((void**)&Q,     g_Q);
    cudaGetSymbolAddress((void**)&K,     g_K);
    cudaGetSymbolAddress((void**)&Vt,    g_Vt);
    cudaGetSymbolAddress((void**)&attn,  g_attn);

    static bool attr_set = false;
    if (!attr_set) {
        cudaFuncSetAttribute(flash_kernel,
                             cudaFuncAttributeMaxDynamicSharedMemorySize, FLASH_SMEM);
        attr_set = true;
    }

    dim3 blk(256);
    const int M = BATCH * SEQ;   // 4096

    // 1) q_lin = x @ Wq
    tgemm_kernel<false><<<dim3(DIM / 128, M / 128, 1), blk>>>(
        x, Wq, qlin, M, INNER, DIM, 0, 0, 0, 0, 1, INNER, nullptr);

    // 2) kv_lin = x @ Wkv
    tgemm_kernel<false><<<dim3(2 * INNER / 128, M / 128, 1), blk>>>(
        x, Wkv, kvlin, M, 2 * INNER, DIM, 0, 0, 0, 0, 1, 2 * INNER, nullptr);

    // 3) rotary + split heads (Q scaled, K natural, V transposed; all tf32-rounded)
    rotary_kernel<<<(BATCH * SEQ * HEADS * 64) / 256, blk>>>(qlin, kvlin, rot, Q, K, Vt);

    // 4) fused attention -> attn (b, n, h*d)
    flash_kernel<<<dim3(SEQ / 128, BH), blk, FLASH_SMEM>>>(Q, K, Vt, attn);

    // 5) out = attn @ Wo + bo
    tgemm_kernel<true><<<dim3(DIM / 128, M / 128, 1), blk>>>(
        attn, Wo, out, M, DIM, INNER, 0, 0, 0, 0, 1, DIM, bo);
}

// round 4
// speedup vs baseline: 3.7144x; 1.4786x over previous
#include <cuda_runtime.h>
#include <math.h>
#include <stdint.h>

#define HEADS  16
#define DHEAD  128
#define BATCH  2
#define SEQ    2048
#define DIM    2048
#define INNER  (HEADS * DHEAD)   // 2048
#define BH     (BATCH * HEADS)   // 32

// ---------------- scratch (allocation-free: __device__ globals) ----------------
__device__ float g_xr   [(size_t)BATCH * SEQ * DIM];        // tf32-rounded x
__device__ float g_Wqr  [(size_t)DIM * INNER];
__device__ float g_Wkvr [(size_t)DIM * 2 * INNER];
__device__ float g_Wor  [(size_t)INNER * DIM];
__device__ float g_qlin [(size_t)BATCH * SEQ * INNER];
__device__ float g_kvlin[(size_t)BATCH * SEQ * 2 * INNER];
__device__ float g_Q    [(size_t)BH * SEQ * DHEAD];
__device__ float g_K    [(size_t)BH * SEQ * DHEAD];
__device__ float g_Vn   [(size_t)BH * SEQ * DHEAD];         // natural (bh,n,d)
__device__ float g_Vt   [(size_t)BH * DHEAD * SEQ];         // (bh,d,n)
__device__ float g_attn [(size_t)BATCH * SEQ * INNER];      // tf32-rounded

__device__ __forceinline__ float f2tf(float f) {
    uint32_t u;
    asm("cvt.rna.tf32.f32 %0, %1;" : "=r"(u) : "f"(f));
    return __uint_as_float(u);
}

#define MMA_TF32(C, A0, A1, A2, A3, B0, B1)                                   \
    asm volatile(                                                             \
        "mma.sync.aligned.m16n8k8.row.col.f32.tf32.tf32.f32 "                 \
        "{%0,%1,%2,%3}, {%4,%5,%6,%7}, {%8,%9}, {%0,%1,%2,%3};"               \
        : "+f"((C)[0]), "+f"((C)[1]), "+f"((C)[2]), "+f"((C)[3])              \
        : "r"(A0), "r"(A1), "r"(A2), "r"(A3), "r"(B0), "r"(B1))

#define CPA16(dst, src)                                                       \
    asm volatile("cp.async.cg.shared.global [%0], [%1], 16;"                  \
                 :: "r"(dst), "l"(src))

// ---------------- elementwise tf32 rounding ----------------
__global__ __launch_bounds__(256) void round_kernel(
    const float4* __restrict__ src, float4* __restrict__ dst, int n4)
{
    int i = blockIdx.x * blockDim.x + threadIdx.x;
    if (i < n4) {
        float4 v = src[i];
        dst[i] = make_float4(f2tf(v.x), f2tf(v.y), f2tf(v.z), f2tf(v.w));
    }
}

// ---------------- TF32 GEMM, 3-stage cp.async pipeline ----------------
// Inputs must be pre-rounded to tf32. A (MxK), B (KxN) row-major contiguous.
#define TG_PA 24
#define TG_PB 132
#define TG_ASTR (128 * TG_PA)     // 3072 floats/stage
#define TG_BSTR (16 * TG_PB)      // 2112 floats/stage
#define TG_BOFF (3 * TG_ASTR)     // Bs base
#define TG_SMEM ((3 * TG_ASTR + 3 * TG_BSTR) * 4)   // 62976 B

template<bool WITH_BIAS>
__global__ __launch_bounds__(256, 2) void tgemm_kernel(
    const float* __restrict__ A, const float* __restrict__ Bm, float* __restrict__ C,
    int M, int Nn, int K,
    long long sA, long long sB, long long sC, long long sC2, int cdiv, int ldc,
    const float* __restrict__ bias)
{
    extern __shared__ float sm[];
    float* As = sm;
    float* Bs = sm + TG_BOFF;

    int z = blockIdx.z;
    A  += (long long)z * sA;
    Bm += (long long)z * sB;
    C  += (long long)(z / cdiv) * sC + (long long)(z % cdiv) * sC2;

    const int bx = blockIdx.x, by = blockIdx.y;
    const int tid  = threadIdx.x;
    const int lane = tid & 31;
    const int wid  = tid >> 5;
    const int warpm = wid >> 2;
    const int warpn = wid & 3;
    const int grp = lane >> 2;
    const int tig = lane & 3;

    const float* Ag = A  + (long long)by * 128 * K;
    const float* Bg = Bm + bx * 128;

    // cp.async mappings
    const int arow = tid >> 2, ac4 = (tid & 3) * 4;          // A: 128 rows x 4 chunks
    const int brow = tid >> 5, bc4 = (tid & 31) * 4;         // B: 16 rows x 32 chunks

    const int T = K >> 4;   // BK = 16

    auto issue = [&](int t, int st) {
        int kt = t * 16;
        #pragma unroll
        for (int i = 0; i < 2; i++) {
            int row = arow + i * 64;
            uint32_t d = (uint32_t)__cvta_generic_to_shared(&As[st * TG_ASTR + row * TG_PA + ac4]);
            CPA16(d, Ag + (long long)row * K + kt + ac4);
        }
        #pragma unroll
        for (int i = 0; i < 2; i++) {
            int row = brow + i * 8;
            uint32_t d = (uint32_t)__cvta_generic_to_shared(&Bs[st * TG_BSTR + row * TG_PB + bc4]);
            CPA16(d, Bg + (long long)(kt + row) * Nn + bc4);
        }
        asm volatile("cp.async.commit_group;");
    };

    float c[4][4][4];
    #pragma unroll
    for (int i = 0; i < 4; i++)
        #pragma unroll
        for (int j = 0; j < 4; j++)
            #pragma unroll
            for (int r = 0; r < 4; r++) c[i][j][r] = 0.0f;

    issue(0, 0);
    issue(1, 1);

    for (int t = 0; t < T; t++) {
        if (t < T - 1) asm volatile("cp.async.wait_group 1;");
        else           asm volatile("cp.async.wait_group 0;");
        __syncthreads();

        const float* as = As + (t % 3) * TG_ASTR;
        const float* bs = Bs + (t % 3) * TG_BSTR;

        #pragma unroll
        for (int s = 0; s < 2; s++) {
            const int kk = 8 * s + 2 * tig;
            uint32_t a[4][4];
            #pragma unroll
            for (int im = 0; im < 4; im++) {
                int r0 = warpm * 64 + im * 16 + grp;
                float2 lo = *(const float2*)&as[r0 * TG_PA + kk];
                float2 hi = *(const float2*)&as[(r0 + 8) * TG_PA + kk];
                a[im][0] = __float_as_uint(lo.x);
                a[im][2] = __float_as_uint(lo.y);
                a[im][1] = __float_as_uint(hi.x);
                a[im][3] = __float_as_uint(hi.y);
            }
            uint32_t b[4][2];
            #pragma unroll
            for (int in_ = 0; in_ < 4; in_++) {
                int n0 = warpn * 32 + in_ * 8 + grp;
                b[in_][0] = __float_as_uint(bs[kk * TG_PB + n0]);
                b[in_][1] = __float_as_uint(bs[(kk + 1) * TG_PB + n0]);
            }
            #pragma unroll
            for (int im = 0; im < 4; im++)
                #pragma unroll
                for (int in_ = 0; in_ < 4; in_++)
                    MMA_TF32(c[im][in_], a[im][0], a[im][1], a[im][2], a[im][3],
                             b[in_][0], b[in_][1]);
        }
        // 3 stages: issue into (t+2)%3 = (t-1)%3, already fully consumed.
        if (t + 2 < T) issue(t + 2, (t + 2) % 3);
    }

    #pragma unroll
    for (int im = 0; im < 4; im++) {
        int row0 = by * 128 + warpm * 64 + im * 16 + grp;
        #pragma unroll
        for (int in_ = 0; in_ < 4; in_++) {
            int col0 = bx * 128 + warpn * 32 + in_ * 8 + 2 * tig;
            float2 v0 = make_float2(c[im][in_][0], c[im][in_][1]);
            float2 v1 = make_float2(c[im][in_][2], c[im][in_][3]);
            if (WITH_BIAS) {
                v0.x += bias[col0]; v0.y += bias[col0 + 1];
                v1.x += bias[col0]; v1.y += bias[col0 + 1];
            }
            *(float2*)(C + (long long)row0 * ldc + col0)       = v0;
            *(float2*)(C + (long long)(row0 + 8) * ldc + col0) = v1;
        }
    }
}

// ---------------- rotary: all writes coalesced, V natural ----------------
__global__ __launch_bounds__(256) void rotary_kernel(
    const float* __restrict__ qlin, const float* __restrict__ kvlin,
    const float* __restrict__ rot,
    float* __restrict__ Q, float* __restrict__ K, float* __restrict__ V)
{
    int idx = blockIdx.x * blockDim.x + threadIdx.x;
    int p = idx & 63;
    int h = (idx >> 6) & (HEADS - 1);
    int n = (idx >> 10) & (SEQ - 1);
    int b = idx >> 21;
    int d0 = 2 * p;

    float c0, s0, c1, s1;
    sincosf(rot[n * DHEAD + d0],     &s0, &c0);
    sincosf(rot[n * DHEAD + d0 + 1], &s1, &c1);

    long long bh = (long long)b * HEADS + h;

    const float* ql = qlin + ((long long)(b * SEQ + n)) * INNER + h * DHEAD;
    float q0 = ql[d0], q1 = ql[d0 + 1];
    const float scale = 0.088388347648318447f;
    float* Qp = Q + (bh * SEQ + n) * DHEAD;
    Qp[d0]     = f2tf((q0 * c0 - q1 * s0) * scale);
    Qp[d0 + 1] = f2tf((q1 * c1 + q0 * s1) * scale);

    const float* kl = kvlin + ((long long)(b * SEQ + n)) * (2 * INNER) + h * DHEAD;
    float k0 = kl[d0], k1 = kl[d0 + 1];
    float* Kp = K + (bh * SEQ + n) * DHEAD;
    Kp[d0]     = f2tf(k0 * c0 - k1 * s0);
    Kp[d0 + 1] = f2tf(k1 * c1 + k0 * s1);

    const float* vl = kvlin + ((long long)(b * SEQ + n)) * (2 * INNER) + INNER + h * DHEAD;
    float* Vp = V + (bh * SEQ + n) * DHEAD;
    Vp[d0]     = f2tf(vl[d0]);
    Vp[d0 + 1] = f2tf(vl[d0 + 1]);
}

// ---------------- V transpose: (bh,n,d) -> (bh,d,n), tiled ----------------
__global__ __launch_bounds__(256) void transpose_kernel(
    const float* __restrict__ V, float* __restrict__ Vt)
{
    __shared__ float tile[32][33];
    int bh = blockIdx.z;
    int n0 = blockIdx.x * 32, d0 = blockIdx.y * 32;
    int tx = threadIdx.x, ty = threadIdx.y;   // 32 x 8

    const float* src = V + (long long)bh * SEQ * DHEAD;
    #pragma unroll
    for (int i = 0; i < 32; i += 8)
        tile[ty + i][tx] = src[(long long)(n0 + ty + i) * DHEAD + d0 + tx];
    __syncthreads();
    float* dst = Vt + (long long)bh * DHEAD * SEQ;
    #pragma unroll
    for (int i = 0; i < 32; i += 8)
        dst[(long long)(d0 + ty + i) * SEQ + n0 + tx] = tile[tx][ty + i];
}

// ---------------- fused flash attention: 512 threads, Q-block 256, KV-tile 32 ----------------
#define PQ 136
#define PK 136
#define PV 40
#define QROWS 256
#define KT 32
#define KS_STR (KT * PK)          // 4352 floats
#define VS_STR (DHEAD * PV)       // 5120 floats
#define QS_SZ  (QROWS * PQ)       // 34816 floats
#define FL_KOFF QS_SZ
#define FL_VOFF (QS_SZ + 2 * KS_STR)
#define FLASH_SMEM ((QS_SZ + 2 * KS_STR + 2 * VS_STR) * 4)   // 215040 B
#define NTILE (SEQ / KT)          // 64

__global__ __launch_bounds__(512, 1) void flash_kernel(
    const float* __restrict__ Qg_, const float* __restrict__ Kg_,
    const float* __restrict__ Vg_, float* __restrict__ attn)
{
    extern __shared__ float sm[];
    float* Qs = sm;
    float* Ks = sm + FL_KOFF;
    float* Vs = sm + FL_VOFF;

    const int qblk = blockIdx.x, bh = blockIdx.y;
    const int b = bh >> 4, h = bh & 15;
    const int tid = threadIdx.x, lane = tid & 31, wid = tid >> 5;
    const int grp = lane >> 2, tig = lane & 3;

    const float* Qg = Qg_ + ((long long)bh * SEQ + qblk * QROWS) * DHEAD;
    const float* Kg = Kg_ + (long long)bh * SEQ * DHEAD;
    const float* Vg = Vg_ + (long long)bh * DHEAD * SEQ;

    auto issue = [&](int it, int buf) {
        const float* ks = Kg + it * KT * DHEAD;
        #pragma unroll
        for (int i = 0; i < 2; i++) {
            int ch = tid + 512 * i;
            int row = ch >> 5, c4 = (ch & 31) * 4;       // 32 rows x 128 floats
            uint32_t d = (uint32_t)__cvta_generic_to_shared(&Ks[buf * KS_STR + row * PK + c4]);
            CPA16(d, ks + row * DHEAD + c4);
        }
        const float* vs = Vg + it * KT;
        #pragma unroll
        for (int i = 0; i < 2; i++) {
            int ch = tid + 512 * i;
            int row = ch >> 3, c4 = (ch & 7) * 4;        // 128 rows x 32 floats
            uint32_t d = (uint32_t)__cvta_generic_to_shared(&Vs[buf * VS_STR + row * PV + c4]);
            CPA16(d, vs + row * SEQ + c4);
        }
        asm volatile("cp.async.commit_group;");
    };

    issue(0, 0);
    issue(1, 1);

    // stage Q (256 x 128), overlaps with in-flight cp.asyncs
    #pragma unroll
    for (int i = 0; i < 16; i++) {
        int ch = tid + 512 * i;
        int row = ch >> 5, c4 = (ch & 31) * 4;
        *(float4*)&Qs[row * PQ + c4] = *(const float4*)(Qg + row * DHEAD + c4);
    }

    float o[16][4];
    #pragma unroll
    for (int f = 0; f < 16; f++)
        #pragma unroll
        for (int r = 0; r < 4; r++) o[f][r] = 0.0f;
    float m0 = -1e30f, m1 = -1e30f, l0 = 0.0f, l1 = 0.0f;

    const int rowA = 16 * wid + grp;

    for (int it = 0; it < NTILE; it++) {
        if (it < NTILE - 1) asm volatile("cp.async.wait_group 1;");
        else                asm volatile("cp.async.wait_group 0;");
        __syncthreads();

        const float* kb = Ks + (it & 1) * KS_STR;
        const float* vb = Vs + (it & 1) * VS_STR;

        // ---- S = Q @ K^T (16 rows x 32 keys per warp) ----
        float sc[4][4];
        #pragma unroll
        for (int f = 0; f < 4; f++)
            #pragma unroll
            for (int r = 0; r < 4; r++) sc[f][r] = 0.0f;

        #pragma unroll
        for (int s = 0; s < 16; s++) {
            const int kk = 8 * s + 2 * tig;
            float2 qa = *(const float2*)&Qs[rowA * PQ + kk];
            float2 qb = *(const float2*)&Qs[(rowA + 8) * PQ + kk];
            uint32_t a0 = __float_as_uint(qa.x), a1 = __float_as_uint(qb.x);
            uint32_t a2 = __float_as_uint(qa.y), a3 = __float_as_uint(qb.y);
            #pragma unroll
            for (int f = 0; f < 4; f++) {
                float2 bk = *(const float2*)&kb[(8 * f + grp) * PK + kk];
                MMA_TF32(sc[f], a0, a1, a2, a3,
                         __float_as_uint(bk.x), __float_as_uint(bk.y));
            }
        }

        // ---- online softmax ----
        float mx0 = -1e30f, mx1 = -1e30f;
        #pragma unroll
        for (int f = 0; f < 4; f++) {
            mx0 = fmaxf(mx0, fmaxf(sc[f][0], sc[f][1]));
            mx1 = fmaxf(mx1, fmaxf(sc[f][2], sc[f][3]));
        }
        mx0 = fmaxf(mx0, __shfl_xor_sync(0xffffffffu, mx0, 1));
        mx0 = fmaxf(mx0, __shfl_xor_sync(0xffffffffu, mx0, 2));
        mx1 = fmaxf(mx1, __shfl_xor_sync(0xffffffffu, mx1, 1));
        mx1 = fmaxf(mx1, __shfl_xor_sync(0xffffffffu, mx1, 2));

        float mn0 = fmaxf(m0, mx0), mn1 = fmaxf(m1, mx1);
        float r0 = __expf(m0 - mn0), r1 = __expf(m1 - mn1);
        l0 *= r0; l1 *= r1;
        #pragma unroll
        for (int f = 0; f < 16; f++) {
            o[f][0] *= r0; o[f][1] *= r0;
            o[f][2] *= r1; o[f][3] *= r1;
        }

        float rs0 = 0.0f, rs1 = 0.0f;
        #pragma unroll
        for (int f = 0; f < 4; f++) {
            float p0 = __expf(sc[f][0] - mn0);
            float p1 = __expf(sc[f][1] - mn0);
            float p2 = __expf(sc[f][2] - mn1);
            float p3 = __expf(sc[f][3] - mn1);
            rs0 += p0 + p1; rs1 += p2 + p3;
            sc[f][0] = f2tf(p0); sc[f][1] = f2tf(p1);
            sc[f][2] = f2tf(p2); sc[f][3] = f2tf(p3);
        }
        rs0 += __shfl_xor_sync(0xffffffffu, rs0, 1);
        rs0 += __shfl_xor_sync(0xffffffffu, rs0, 2);
        rs1 += __shfl_xor_sync(0xffffffffu, rs1, 1);
        rs1 += __shfl_xor_sync(0xffffffffu, rs1, 2);
        l0 += rs0; l1 += rs1;
        m0 = mn0; m1 = mn1;

        // ---- O += P @ V ----
        #pragma unroll
        for (int s = 0; s < 4; s++) {
            uint32_t a0 = __float_as_uint(sc[s][0]);
            uint32_t a1 = __float_as_uint(sc[s][2]);
            uint32_t a2 = __float_as_uint(sc[s][1]);
            uint32_t a3 = __float_as_uint(sc[s][3]);
            const int kk = 8 * s + 2 * tig;
            #pragma unroll
            for (int f = 0; f < 16; f++) {
                float2 bv = *(const float2*)&vb[(8 * f + grp) * PV + kk];
                MMA_TF32(o[f], a0, a1, a2, a3,
                         __float_as_uint(bv.x), __float_as_uint(bv.y));
            }
        }

        __syncthreads();
        if (it + 2 < NTILE) issue(it + 2, it & 1);
    }

    // epilogue: O /= l, scatter to (b, n, h*d), tf32-rounded for GEMM-7
    float inv0 = 1.0f / l0, inv1 = 1.0f / l1;
    int nrow = qblk * QROWS + 16 * wid + grp;
    float* outp = attn + ((long long)(b * SEQ + nrow)) * INNER + h * DHEAD;
    #pragma unroll
    for (int f = 0; f < 16; f++) {
        int col = 8 * f + 2 * tig;
        *(float2*)(outp + col) =
            make_float2(f2tf(o[f][0] * inv0), f2tf(o[f][1] * inv0));
        *(float2*)(outp + (long long)8 * INNER + col) =
            make_float2(f2tf(o[f][2] * inv1), f2tf(o[f][3] * inv1));
    }
}

// ---------------- launch ----------------
extern "C" void kernel_launch(void* const* d_in, const int* in_sizes, int n_in,
                              void* d_out, int out_size)
{
    const float* x   = (const float*)d_in[0];
    const float* rot = (const float*)d_in[1];
    const float* Wq  = (const float*)d_in[2];
    const float* Wkv = (const float*)d_in[3];
    const float* Wo  = (const float*)d_in[4];
    const float* bo  = (const float*)d_in[5];
    float* out = (float*)d_out;

    float *xr, *Wqr, *Wkvr, *Wor, *qlin, *kvlin, *Q, *K, *Vn, *Vt, *attn;
    cudaGetSymbolAddress((void**)&xr,    g_xr);
    cudaGetSymbolAddress((void**)&Wqr,   g_Wqr);
    cudaGetSymbolAddress((void**)&Wkvr,  g_Wkvr);
    cudaGetSymbolAddress((void**)&Wor,   g_Wor);
    cudaGetSymbolAddress((void**)&qlin,  g_qlin);
    cudaGetSymbolAddress((void**)&kvlin, g_kvlin);
    cudaGetSymbolAddress((void**)&Q,     g_Q);
    cudaGetSymbolAddress((void**)&K,     g_K);
    cudaGetSymbolAddress((void**)&Vn,    g_Vn);
    cudaGetSymbolAddress((void**)&Vt,    g_Vt);
    cudaGetSymbolAddress((void**)&attn,  g_attn);

    cudaFuncSetAttribute(flash_kernel,
                         cudaFuncAttributeMaxDynamicSharedMemorySize, FLASH_SMEM);
    cudaFuncSetAttribute(tgemm_kernel<false>,
                         cudaFuncAttributeMaxDynamicSharedMemorySize, TG_SMEM);
    cudaFuncSetAttribute(tgemm_kernel<true>,
                         cudaFuncAttributeMaxDynamicSharedMemorySize, TG_SMEM);

    dim3 blk(256);
    const int M = BATCH * SEQ;   // 4096

    // 0) pre-round inputs to tf32 (enables raw cp.async in GEMMs)
    round_kernel<<<(M * DIM / 4 + 255) / 256, blk>>>((const float4*)x, (float4*)xr, M * DIM / 4);
    round_kernel<<<(DIM * INNER / 4 + 255) / 256, blk>>>((const float4*)Wq, (float4*)Wqr, DIM * INNER / 4);
    round_kernel<<<(DIM * 2 * INNER / 4 + 255) / 256, blk>>>((const float4*)Wkv, (float4*)Wkvr, DIM * 2 * INNER / 4);
    round_kernel<<<(INNER * DIM / 4 + 255) / 256, blk>>>((const float4*)Wo, (float4*)Wor, INNER * DIM / 4);

    // 1) q_lin = xr @ Wqr
    tgemm_kernel<false><<<dim3(INNER / 128, M / 128, 1), blk, TG_SMEM>>>(
        xr, Wqr, qlin, M, INNER, DIM, 0, 0, 0, 0, 1, INNER, nullptr);

    // 2) kv_lin = xr @ Wkvr
    tgemm_kernel<false><<<dim3(2 * INNER / 128, M / 128, 1), blk, TG_SMEM>>>(
        xr, Wkvr, kvlin, M, 2 * INNER, DIM, 0, 0, 0, 0, 1, 2 * INNER, nullptr);

    // 3) rotary + head split (all coalesced, tf32-rounded)
    rotary_kernel<<<(BATCH * SEQ * HEADS * 64) / 256, blk>>>(qlin, kvlin, rot, Q, K, Vn);

    // 4) V transpose (coalesced both sides)
    transpose_kernel<<<dim3(SEQ / 32, DHEAD / 32, BH), dim3(32, 8)>>>(Vn, Vt);

    // 5) fused attention -> attn (b, n, h*d)
    flash_kernel<<<dim3(SEQ / QROWS, BH), dim3(512), FLASH_SMEM>>>(Q, K, Vt, attn);

    // 6) out = attn @ Wor + bo
    tgemm_kernel<true><<<dim3(DIM / 128, M / 128, 1), blk, TG_SMEM>>>(
        attn, Wor, out, M, DIM, INNER, 0, 0, 0, 0, 1, DIM, bo);
}

// round 6
// speedup vs baseline: 6.8482x; 1.8437x over previous
#include <cuda_runtime.h>
#include <cuda_fp16.h>
#include <math.h>
#include <stdint.h>

#define HEADS  16
#define DHEAD  128
#define BATCH  2
#define SEQ    2048
#define DIM    2048
#define INNER  (HEADS * DHEAD)   // 2048
#define BH     (BATCH * HEADS)   // 32

// ---------------- scratch (allocation-free: __device__ globals) ----------------
__device__ __half g_xh   [(size_t)BATCH * SEQ * DIM];
__device__ __half g_Wqh  [(size_t)DIM * INNER];
__device__ __half g_Wkvh [(size_t)DIM * 2 * INNER];
__device__ __half g_Woh  [(size_t)INNER * DIM];
__device__ float  g_qlin [(size_t)BATCH * SEQ * INNER];
__device__ float  g_kvlin[(size_t)BATCH * SEQ * 2 * INNER];
__device__ __half g_Qh   [(size_t)BH * SEQ * DHEAD];
__device__ __half g_Kh   [(size_t)BH * SEQ * DHEAD];
__device__ __half g_Vnh  [(size_t)BH * SEQ * DHEAD];
__device__ __half g_Vth  [(size_t)BH * DHEAD * SEQ];
__device__ __half g_attnh[(size_t)BATCH * SEQ * INNER];

__device__ __forceinline__ uint32_t pack2(float a, float b) {
    __half2 h = __floats2half2_rn(a, b);
    return *reinterpret_cast<uint32_t*>(&h);
}

#define MMA_F16(C, A0, A1, A2, A3, B0, B1)                                    \
    asm volatile(                                                             \
        "mma.sync.aligned.m16n8k16.row.col.f32.f16.f16.f32 "                  \
        "{%0,%1,%2,%3}, {%4,%5,%6,%7}, {%8,%9}, {%0,%1,%2,%3};"               \
        : "+f"((C)[0]), "+f"((C)[1]), "+f"((C)[2]), "+f"((C)[3])              \
        : "r"(A0), "r"(A1), "r"(A2), "r"(A3), "r"(B0), "r"(B1))

#define LDSM4(R0, R1, R2, R3, ADDR)                                           \
    asm volatile("ldmatrix.sync.aligned.m8n8.x4.shared.b16 {%0,%1,%2,%3},[%4];" \
                 : "=r"(R0), "=r"(R1), "=r"(R2), "=r"(R3) : "r"(ADDR))

#define LDSM4T(R0, R1, R2, R3, ADDR)                                          \
    asm volatile("ldmatrix.sync.aligned.m8n8.x4.trans.shared.b16 {%0,%1,%2,%3},[%4];" \
                 : "=r"(R0), "=r"(R1), "=r"(R2), "=r"(R3) : "r"(ADDR))

#define CPA16(dst, src)                                                       \
    asm volatile("cp.async.cg.shared.global [%0], [%1], 16;"                  \
                 :: "r"(dst), "l"(src))

// ---------------- fp32 -> fp16 conversion ----------------
__global__ __launch_bounds__(256) void cvt_kernel(
    const float4* __restrict__ src, uint2* __restrict__ dst, int n4)
{
    int i = blockIdx.x * blockDim.x + threadIdx.x;
    if (i < n4) {
        float4 v = src[i];
        dst[i] = make_uint2(pack2(v.x, v.y), pack2(v.z, v.w));
    }
}

// ---------------- fp16 GEMM, m16n8k16 + ldmatrix, 3-stage cp.async ----------------
// A (MxK) half row-major, B (KxN) half row-major, C fp32.
#define HG_PA 40                      // A row pitch (halves): 32 data + 8 pad
#define HG_PB 136                     // B row pitch (halves): 128 data + 8 pad
#define HG_ASTR (128 * HG_PA)         // 5120 halves/stage
#define HG_BSTR (32 * HG_PB)          // 4352 halves/stage
#define HG_BOFF (3 * HG_ASTR)
#define HG_SMEM ((3 * HG_ASTR + 3 * HG_BSTR) * 2)   // 56832 B

template<bool WITH_BIAS>
__global__ __launch_bounds__(256, 2) void hgemm_kernel(
    const __half* __restrict__ A, const __half* __restrict__ Bm,
    float* __restrict__ C, int M, int Nn, int K, int ldc,
    const float* __restrict__ bias)
{
    extern __shared__ __half smh[];
    __half* As = smh;
    __half* Bs = smh + HG_BOFF;
    const uint32_t as_u = (uint32_t)__cvta_generic_to_shared(As);
    const uint32_t bs_u = (uint32_t)__cvta_generic_to_shared(Bs);

    const int bx = blockIdx.x, by = blockIdx.y;
    const int tid  = threadIdx.x;
    const int lane = tid & 31;
    const int wid  = tid >> 5;
    const int warpm = wid >> 2;       // 0..1 -> 64 rows
    const int warpn = wid & 3;        // 0..3 -> 32 cols
    const int grp = lane >> 2;
    const int tig = lane & 3;

    const __half* Ag = A  + (long long)by * 128 * K;
    const __half* Bg = Bm + bx * 128;

    const int T = K >> 5;             // BK = 32

    auto issue = [&](int t, int st) {
        int kt = t * 32;
        // A: 128 rows x 4 chunks(16B) = 512 chunks
        #pragma unroll
        for (int i = 0; i < 2; i++) {
            int c = tid + 256 * i;
            int row = c >> 2, cc = (c & 3) * 8;
            uint32_t d = as_u + (st * HG_ASTR + row * HG_PA + cc) * 2;
            CPA16(d, Ag + (long long)row * K + kt + cc);
        }
        // B: 32 rows x 16 chunks = 512 chunks
        #pragma unroll
        for (int i = 0; i < 2; i++) {
            int c = tid + 256 * i;
            int row = c >> 4, cc = (c & 15) * 8;
            uint32_t d = bs_u + (st * HG_BSTR + row * HG_PB + cc) * 2;
            CPA16(d, Bg + (long long)(kt + row) * Nn + cc);
        }
        asm volatile("cp.async.commit_group;");
    };

    float c[4][4][4];
    #pragma unroll
    for (int i = 0; i < 4; i++)
        #pragma unroll
        for (int j = 0; j < 4; j++)
            #pragma unroll
            for (int r = 0; r < 4; r++) c[i][j][r] = 0.0f;

    issue(0, 0);
    issue(1, 1);

    for (int t = 0; t < T; t++) {
        if (t < T - 1) asm volatile("cp.async.wait_group 1;");
        else           asm volatile("cp.async.wait_group 0;");
        __syncthreads();

        const uint32_t asb = as_u + (t % 3) * HG_ASTR * 2;
        const uint32_t bsb = bs_u + (t % 3) * HG_BSTR * 2;

        #pragma unroll
        for (int s = 0; s < 2; s++) {
            const int ks = s * 16;
            uint32_t a[4][4];
            #pragma unroll
            for (int im = 0; im < 4; im++) {
                int row = warpm * 64 + im * 16 + (lane & 15);
                uint32_t ad = asb + (row * HG_PA + ks + ((lane >> 4) * 8)) * 2;
                LDSM4(a[im][0], a[im][1], a[im][2], a[im][3], ad);
            }
            uint32_t bb[4][2];
            #pragma unroll
            for (int ib = 0; ib < 2; ib++) {
                int row = ks + (lane & 15);
                int col = warpn * 32 + ib * 16 + ((lane >> 4) * 8);
                uint32_t bd = bsb + (row * HG_PB + col) * 2;
                LDSM4T(bb[2 * ib][0], bb[2 * ib][1], bb[2 * ib + 1][0], bb[2 * ib + 1][1], bd);
            }
            #pragma unroll
            for (int im = 0; im < 4; im++)
                #pragma unroll
                for (int jn = 0; jn < 4; jn++)
                    MMA_F16(c[im][jn], a[im][0], a[im][1], a[im][2], a[im][3],
                            bb[jn][0], bb[jn][1]);
        }
        if (t + 2 < T) issue(t + 2, (t + 2) % 3);
    }

    #pragma unroll
    for (int im = 0; im < 4; im++) {
        int row0 = by * 128 + warpm * 64 + im * 16 + grp;
        #pragma unroll
        for (int jn = 0; jn < 4; jn++) {
            int col0 = bx * 128 + warpn * 32 + jn * 8 + 2 * tig;
            float2 v0 = make_float2(c[im][jn][0], c[im][jn][1]);
            float2 v1 = make_float2(c[im][jn][2], c[im][jn][3]);
            if (WITH_BIAS) {
                v0.x += bias[col0]; v0.y += bias[col0 + 1];
                v1.x += bias[col0]; v1.y += bias[col0 + 1];
            }
            *(float2*)(C + (long long)row0 * ldc + col0)       = v0;
            *(float2*)(C + (long long)(row0 + 8) * ldc + col0) = v1;
        }
    }
}

// ---------------- rotary + scale + head split (fp32 in, fp16 out) ----------------
__global__ __launch_bounds__(256) void rotary_kernel(
    const float* __restrict__ qlin, const float* __restrict__ kvlin,
    const float* __restrict__ rot,
    __half* __restrict__ Q, __half* __restrict__ K, __half* __restrict__ V)
{
    int idx = blockIdx.x * blockDim.x + threadIdx.x;
    int p = idx & 63;
    int h = (idx >> 6) & (HEADS - 1);
    int n = (idx >> 10) & (SEQ - 1);
    int b = idx >> 21;
    int d0 = 2 * p;

    float c0, s0, c1, s1;
    sincosf(rot[n * DHEAD + d0],     &s0, &c0);
    sincosf(rot[n * DHEAD + d0 + 1], &s1, &c1);

    long long bh = (long long)b * HEADS + h;

    const float* ql = qlin + ((long long)(b * SEQ + n)) * INNER + h * DHEAD;
    float q0 = ql[d0], q1 = ql[d0 + 1];
    const float scale = 0.088388347648318447f;
    *(__half2*)(Q + (bh * SEQ + n) * DHEAD + d0) =
        __floats2half2_rn((q0 * c0 - q1 * s0) * scale, (q1 * c1 + q0 * s1) * scale);

    const float* kl = kvlin + ((long long)(b * SEQ + n)) * (2 * INNER) + h * DHEAD;
    float k0 = kl[d0], k1 = kl[d0 + 1];
    *(__half2*)(K + (bh * SEQ + n) * DHEAD + d0) =
        __floats2half2_rn(k0 * c0 - k1 * s0, k1 * c1 + k0 * s1);

    const float* vl = kvlin + ((long long)(b * SEQ + n)) * (2 * INNER) + INNER + h * DHEAD;
    *(__half2*)(V + (bh * SEQ + n) * DHEAD + d0) =
        __floats2half2_rn(vl[d0], vl[d0 + 1]);
}

// ---------------- V transpose: (bh,n,d) -> (bh,d,n) half ----------------
__global__ __launch_bounds__(256) void transpose_kernel(
    const __half* __restrict__ V, __half* __restrict__ Vt)
{
    __shared__ __half tile[32][34];
    int bh = blockIdx.z;
    int n0 = blockIdx.x * 32, d0 = blockIdx.y * 32;
    int tx = threadIdx.x, ty = threadIdx.y;   // 32 x 8

    const __half* src = V + (long long)bh * SEQ * DHEAD;
    #pragma unroll
    for (int i = 0; i < 32; i += 8)
        tile[ty + i][tx] = src[(long long)(n0 + ty + i) * DHEAD + d0 + tx];
    __syncthreads();
    __half* dst = Vt + (long long)bh * DHEAD * SEQ;
    #pragma unroll
    for (int i = 0; i < 32; i += 8)
        dst[(long long)(d0 + ty + i) * SEQ + n0 + tx] = tile[tx][ty + i];
}

// ---------------- fused flash attention (fp16): 512 thr, Q-block 256, KV-tile 32 ----------------
#define FPQ 136
#define FPK 136
#define FPV 40
#define QROWS 256
#define KT 32
#define FKS_STR (KT * FPK)            // 4352 halves
#define FVS_STR (DHEAD * FPV)         // 5120 halves
#define FQS_SZ  (QROWS * FPQ)         // 34816 halves
#define FL_KOFF FQS_SZ
#define FL_VOFF (FQS_SZ + 3 * FKS_STR)
#define FLASH_SMEM ((FQS_SZ + 3 * FKS_STR + 3 * FVS_STR) * 2)   // 126464 B
#define NTILE (SEQ / KT)              // 64

__global__ __launch_bounds__(512, 1) void flash_kernel(
    const __half* __restrict__ Qg_, const __half* __restrict__ Kg_,
    const __half* __restrict__ Vg_, __half* __restrict__ attn)
{
    extern __shared__ __half fsm[];
    __half* Qs = fsm;
    const uint32_t qs_u = (uint32_t)__cvta_generic_to_shared(Qs);
    const uint32_t ks_u = qs_u + FL_KOFF * 2;
    const uint32_t vs_u = qs_u + FL_VOFF * 2;

    const int qblk = blockIdx.x, bh = blockIdx.y;
    const int b = bh >> 4, h = bh & 15;
    const int tid = threadIdx.x, lane = tid & 31, wid = tid >> 5;
    const int grp = lane >> 2, tig = lane & 3;

    const __half* Qg = Qg_ + ((long long)bh * SEQ + qblk * QROWS) * DHEAD;
    const __half* Kg = Kg_ + (long long)bh * SEQ * DHEAD;
    const __half* Vg = Vg_ + (long long)bh * DHEAD * SEQ;

    auto issue = [&](int it, int buf) {
        // K tile: 32 rows x 128 halves = 512 x 16B chunks
        {
            int row = tid >> 4, cc = (tid & 15) * 8;
            uint32_t d = ks_u + (buf * FKS_STR + row * FPK + cc) * 2;
            CPA16(d, Kg + (long long)(it * KT + row) * DHEAD + cc);
        }
        // V tile: 128 d-rows x 32 halves = 512 x 16B chunks
        {
            int row = tid >> 2, cc = (tid & 3) * 8;
            uint32_t d = vs_u + (buf * FVS_STR + row * FPV + cc) * 2;
            CPA16(d, Vg + (long long)row * SEQ + it * KT + cc);
        }
        asm volatile("cp.async.commit_group;");
    };

    issue(0, 0);
    issue(1, 1);

    // stage Q (256 rows x 128 halves = 4096 x 16B chunks; 512 threads x 8 iters)
    #pragma unroll
    for (int i = 0; i < 8; i++) {
        int ch = tid + 512 * i;
        int row = ch >> 4, cc = (ch & 15) * 8;
        *(uint4*)&Qs[row * FPQ + cc] = *(const uint4*)(Qg + row * DHEAD + cc);
    }

    float o[16][4];
    #pragma unroll
    for (int f = 0; f < 16; f++)
        #pragma unroll
        for (int r = 0; r < 4; r++) o[f][r] = 0.0f;
    float m0 = -1e30f, m1 = -1e30f, l0 = 0.0f, l1 = 0.0f;

    for (int it = 0; it < NTILE; it++) {
        if (it < NTILE - 1) asm volatile("cp.async.wait_group 1;");
        else                asm volatile("cp.async.wait_group 0;");
        __syncthreads();

        const uint32_t kb = ks_u + (it % 3) * FKS_STR * 2;
        const uint32_t vb = vs_u + (it % 3) * FVS_STR * 2;

        // ---- S = Q @ K^T : 16 rows x 32 keys per warp ----
        float sc[4][4];
        #pragma unroll
        for (int f = 0; f < 4; f++)
            #pragma unroll
            for (int r = 0; r < 4; r++) sc[f][r] = 0.0f;

        #pragma unroll
        for (int s = 0; s < 8; s++) {
            const int ks = s * 16;
            uint32_t a0, a1, a2, a3;
            {
                int row = wid * 16 + (lane & 15);
                uint32_t ad = qs_u + (row * FPQ + ks + ((lane >> 4) * 8)) * 2;
                LDSM4(a0, a1, a2, a3, ad);
            }
            #pragma unroll
            for (int pf = 0; pf < 2; pf++) {
                int j = lane >> 3;
                int krow = pf * 16 + ((j >> 1) * 8) + (lane & 7);
                uint32_t bd = kb + (krow * FPK + ks + ((j & 1) * 8)) * 2;
                uint32_t r0, r1, r2, r3;
                LDSM4(r0, r1, r2, r3, bd);
                MMA_F16(sc[2 * pf],     a0, a1, a2, a3, r0, r1);
                MMA_F16(sc[2 * pf + 1], a0, a1, a2, a3, r2, r3);
            }
        }

        // ---- online softmax ----
        float mx0 = -1e30f, mx1 = -1e30f;
        #pragma unroll
        for (int f = 0; f < 4; f++) {
            mx0 = fmaxf(mx0, fmaxf(sc[f][0], sc[f][1]));
            mx1 = fmaxf(mx1, fmaxf(sc[f][2], sc[f][3]));
        }
        mx0 = fmaxf(mx0, __shfl_xor_sync(0xffffffffu, mx0, 1));
        mx0 = fmaxf(mx0, __shfl_xor_sync(0xffffffffu, mx0, 2));
        mx1 = fmaxf(mx1, __shfl_xor_sync(0xffffffffu, mx1, 1));
        mx1 = fmaxf(mx1, __shfl_xor_sync(0xffffffffu, mx1, 2));

        float mn0 = fmaxf(m0, mx0), mn1 = fmaxf(m1, mx1);
        float r0s = __expf(m0 - mn0), r1s = __expf(m1 - mn1);
        l0 *= r0s; l1 *= r1s;
        #pragma unroll
        for (int f = 0; f < 16; f++) {
            o[f][0] *= r0s; o[f][1] *= r0s;
            o[f][2] *= r1s; o[f][3] *= r1s;
        }

        float rs0 = 0.0f, rs1 = 0.0f;
        #pragma unroll
        for (int f = 0; f < 4; f++) {
            sc[f][0] = __expf(sc[f][0] - mn0);
            sc[f][1] = __expf(sc[f][1] - mn0);
            sc[f][2] = __expf(sc[f][2] - mn1);
            sc[f][3] = __expf(sc[f][3] - mn1);
            rs0 += sc[f][0] + sc[f][1];
            rs1 += sc[f][2] + sc[f][3];
        }
        rs0 += __shfl_xor_sync(0xffffffffu, rs0, 1);
        rs0 += __shfl_xor_sync(0xffffffffu, rs0, 2);
        rs1 += __shfl_xor_sync(0xffffffffu, rs1, 1);
        rs1 += __shfl_xor_sync(0xffffffffu, rs1, 2);
        l0 += rs0; l1 += rs1;
        m0 = mn0; m1 = mn1;

        // ---- O += P @ V ----
        #pragma unroll
        for (int s = 0; s < 2; s++) {
            uint32_t a0 = pack2(sc[2 * s][0],     sc[2 * s][1]);
            uint32_t a1 = pack2(sc[2 * s][2],     sc[2 * s][3]);
            uint32_t a2 = pack2(sc[2 * s + 1][0], sc[2 * s + 1][1]);
            uint32_t a3 = pack2(sc[2 * s + 1][2], sc[2 * s + 1][3]);
            #pragma unroll
            for (int pf = 0; pf < 8; pf++) {
                int j = lane >> 3;
                int drow = pf * 16 + ((j >> 1) * 8) + (lane & 7);
                uint32_t bd = vb + (drow * FPV + s * 16 + ((j & 1) * 8)) * 2;
                uint32_t r0, r1, r2, r3;
                LDSM4(r0, r1, r2, r3, bd);
                MMA_F16(o[2 * pf],     a0, a1, a2, a3, r0, r1);
                MMA_F16(o[2 * pf + 1], a0, a1, a2, a3, r2, r3);
            }
        }

        if (it + 2 < NTILE) issue(it + 2, (it + 2) % 3);
    }

    // epilogue: O /= l, scatter to (b, n, h*d) as half
    float inv0 = 1.0f / l0, inv1 = 1.0f / l1;
    int nrow = qblk * QROWS + 16 * wid + grp;
    __half* outp = attn + ((long long)(b * SEQ + nrow)) * INNER + h * DHEAD;
    #pragma unroll
    for (int f = 0; f < 16; f++) {
        int col = 8 * f + 2 * tig;
        *(__half2*)(outp + col) = __floats2half2_rn(o[f][0] * inv0, o[f][1] * inv0);
        *(__half2*)(outp + (long long)8 * INNER + col) =
            __floats2half2_rn(o[f][2] * inv1, o[f][3] * inv1);
    }
}

// ---------------- launch ----------------
extern "C" void kernel_launch(void* const* d_in, const int* in_sizes, int n_in,
                              void* d_out, int out_size)
{
    const float* x   = (const float*)d_in[0];
    const float* rot = (const float*)d_in[1];
    const float* Wq  = (const float*)d_in[2];
    const float* Wkv = (const float*)d_in[3];
    const float* Wo  = (const float*)d_in[4];
    const float* bo  = (const float*)d_in[5];
    float* out = (float*)d_out;

    __half *xh, *Wqh, *Wkvh, *Woh, *Qh, *Kh, *Vnh, *Vth, *attnh;
    float *qlin, *kvlin;
    cudaGetSymbolAddress((void**)&xh,    g_xh);
    cudaGetSymbolAddress((void**)&Wqh,   g_Wqh);
    cudaGetSymbolAddress((void**)&Wkvh,  g_Wkvh);
    cudaGetSymbolAddress((void**)&Woh,   g_Woh);
    cudaGetSymbolAddress((void**)&qlin,  g_qlin);
    cudaGetSymbolAddress((void**)&kvlin, g_kvlin);
    cudaGetSymbolAddress((void**)&Qh,    g_Qh);
    cudaGetSymbolAddress((void**)&Kh,    g_Kh);
    cudaGetSymbolAddress((void**)&Vnh,   g_Vnh);
    cudaGetSymbolAddress((void**)&Vth,   g_Vth);
    cudaGetSymbolAddress((void**)&attnh, g_attnh);

    cudaFuncSetAttribute(flash_kernel,
                         cudaFuncAttributeMaxDynamicSharedMemorySize, FLASH_SMEM);
    cudaFuncSetAttribute(hgemm_kernel<false>,
                         cudaFuncAttributeMaxDynamicSharedMemorySize, HG_SMEM);
    cudaFuncSetAttribute(hgemm_kernel<true>,
                         cudaFuncAttributeMaxDynamicSharedMemorySize, HG_SMEM);

    dim3 blk(256);
    const int M = BATCH * SEQ;   // 4096

    // 0) convert inputs to fp16
    cvt_kernel<<<(M * DIM / 4) / 256, blk>>>((const float4*)x, (uint2*)xh, M * DIM / 4);
    cvt_kernel<<<(DIM * INNER / 4) / 256, blk>>>((const float4*)Wq, (uint2*)Wqh, DIM * INNER / 4);
    cvt_kernel<<<(DIM * 2 * INNER / 4) / 256, blk>>>((const float4*)Wkv, (uint2*)Wkvh, DIM * 2 * INNER / 4);
    cvt_kernel<<<(INNER * DIM / 4) / 256, blk>>>((const float4*)Wo, (uint2*)Woh, INNER * DIM / 4);

    // 1) q_lin = xh @ Wqh   (fp32 out)
    hgemm_kernel<false><<<dim3(INNER / 128, M / 128), blk, HG_SMEM>>>(
        xh, Wqh, qlin, M, INNER, DIM, INNER, nullptr);

    // 2) kv_lin = xh @ Wkvh
    hgemm_kernel<false><<<dim3(2 * INNER / 128, M / 128), blk, HG_SMEM>>>(
        xh, Wkvh, kvlin, M, 2 * INNER, DIM, 2 * INNER, nullptr);

    // 3) rotary + head split -> half Q/K/V
    rotary_kernel<<<(BATCH * SEQ * HEADS * 64) / 256, blk>>>(qlin, kvlin, rot, Qh, Kh, Vnh);

    // 4) V transpose
    transpose_kernel<<<dim3(SEQ / 32, DHEAD / 32, BH), dim3(32, 8)>>>(Vnh, Vth);

    // 5) fused attention -> attnh (half)
    flash_kernel<<<dim3(SEQ / QROWS, BH), dim3(512), FLASH_SMEM>>>(Qh, Kh, Vth, attnh);

    // 6) out = attnh @ Woh + bo  (fp32 out)
    hgemm_kernel<true><<<dim3(DIM / 128, M / 128), blk, HG_SMEM>>>(
        attnh, Woh, out, M, DIM, INNER, DIM, bo);
}